// round 12
// baseline (speedup 1.0000x reference)
#include <cuda_runtime.h>
#include <cuda_bf16.h>
#include <cstdint>

// ---------------- problem constants ----------------
#define BB     128
#define CC     4
#define LL     10000
#define KK     20
#define NN     128
#define POUT   9980            // ceil((L-K)/stride), stride=1
#define TP     10016           // padded pair-row count (t in [0, 9998], zero-padded)
#define TILE_M 128
#define NTILE_P 78             // ceil(9980/128)
#define NUNITS (BB * NTILE_P * 2)  // 19968 work units (p-tile x n-half)
#define KSTEPS 20              // 320 / 16
#define GRID   444             // 3 CTAs/SM x 148 SMs, single wave; even -> nh stable

// ---------------- device scratch (static, no runtime alloc) ----------------
__device__ uint4 g_pb4[(size_t)BB * TP * 2];   // pair bf16 [b][t][16], 2 x uint4 per row
__device__ uint4 g_wb4[NN * 40];               // W bf16 [n][320], 40 x uint4 per n-row

// ---------------- smem layout (dynamic) ----------------
// Warp-private stage: each warp owns 52 rows (32 outputs + 19 halo, padded),
// double-buffered. No CTA barrier needed in the main loop.
#define WROWS        52
#define STAGE_PITCH  48
#define WSTAGE_BYTES (WROWS * STAGE_PITCH)         // 2496 per warp per buffer
#define WSLOT_BYTES  (2 * WSTAGE_BYTES)            // 4992 per warp
#define SMEM_STAGE   0                             // [4 warps][2 buf][2496]
#define SMEM_W       (4 * WSLOT_BYTES)             // 19968
#define WPITCH       656                           // 328 bf16 per n-row (8-elem pad)
#define SMEM_TOTAL   (SMEM_W + 64 * WPITCH)        // 19968 + 41984 = 61952 (x3 = 185856)

// ---------------- helpers ----------------
__device__ __forceinline__ uint32_t smem_u32(const void* p) {
    uint32_t a;
    asm("{ .reg .u64 t; cvta.to.shared.u64 t, %1; cvt.u32.u64 %0, t; }" : "=r"(a) : "l"(p));
    return a;
}
__device__ __forceinline__ void ldmatrix_x4(uint32_t* r, uint32_t addr) {
    asm volatile("ldmatrix.sync.aligned.m8n8.x4.shared.b16 {%0,%1,%2,%3}, [%4];"
                 : "=r"(r[0]), "=r"(r[1]), "=r"(r[2]), "=r"(r[3]) : "r"(addr));
}
__device__ __forceinline__ void mma_bf16(float* c, const uint32_t* a, const uint32_t* b) {
    asm volatile(
        "mma.sync.aligned.m16n8k16.row.col.f32.bf16.bf16.f32 "
        "{%0,%1,%2,%3}, {%4,%5,%6,%7}, {%8,%9}, {%0,%1,%2,%3};"
        : "+f"(c[0]), "+f"(c[1]), "+f"(c[2]), "+f"(c[3])
        : "r"(a[0]), "r"(a[1]), "r"(a[2]), "r"(a[3]), "r"(b[0]), "r"(b[1]));
}
__device__ __forceinline__ void cp_async16(uint32_t saddr, const void* gaddr) {
    asm volatile("cp.async.ca.shared.global [%0], [%1], 16;" :: "r"(saddr), "l"(gaddr) : "memory");
}
__device__ __forceinline__ void cp_async_commit() {
    asm volatile("cp.async.commit_group;" ::: "memory");
}
__device__ __forceinline__ void cp_async_wait0() {
    asm volatile("cp.async.wait_group 0;" ::: "memory");
}

// ---------------- merged prep kernel ----------------
__global__ void prep_all_kernel(const float* __restrict__ x, const float* __restrict__ W) {
    int gid = blockIdx.x * blockDim.x + threadIdx.x;   // gid = b*TP + t
    if (gid < BB * TP) {
        int b = gid / TP;
        int t = gid % TP;
        uint4 lo = make_uint4(0, 0, 0, 0), hi = lo;
        if (t <= LL - 2) {
            float xa[4], xb[4];
#pragma unroll
            for (int i = 0; i < 4; i++) xa[i] = x[((size_t)b * CC + i) * LL + t];
#pragma unroll
            for (int j = 0; j < 4; j++) xb[j] = x[((size_t)b * CC + j) * LL + t + 1];
            unsigned u[8];
#pragma unroll
            for (int i = 0; i < 4; i++) {
#pragma unroll
                for (int jh = 0; jh < 2; jh++) {
                    __nv_bfloat162 h = __floats2bfloat162_rn(xa[i] * xb[2 * jh], xa[i] * xb[2 * jh + 1]);
                    u[i * 2 + jh] = *reinterpret_cast<unsigned*>(&h);
                }
            }
            lo = make_uint4(u[0], u[1], u[2], u[3]);
            hi = make_uint4(u[4], u[5], u[6], u[7]);
        }
        g_pb4[(size_t)gid * 2]     = lo;
        g_pb4[(size_t)gid * 2 + 1] = hi;
    }
    if (gid < KK * CC * CC * NN) {
        int n = gid / 320;
        int rem = gid % 320;            // rem = l*16 + (i*4 + j)
        int l = rem >> 4;
        int c = rem & 15;
        int i = c >> 2, j = c & 3;
        float v = W[(((l * CC + i) * CC + j) * NN) + n];
        reinterpret_cast<__nv_bfloat16*>(g_wb4)[gid] = __float2bfloat16(v);
    }
}

// ---------------- main persistent GEMM kernel ----------------
// Work unit: 128 p-rows x 64 n-cols; 4 warps, each 32m x 64n, WARP-PRIVATE stage.
// Warp w covers p-rows [p0+32w, p0+32w+51] (incl. K-1 halo) in its own smem slice,
// prefetched with its own cp.async groups. NO __syncthreads in the main loop ->
// warps drift across units, overlapping epilogue/LDSM with other warps' MMA.
__global__ void __launch_bounds__(128, 3) markonv_hmma_kernel(float* __restrict__ out) {
    extern __shared__ char smem[];
    const uint32_t smemS = smem_u32(smem);
    const int tid  = threadIdx.x;
    const int lane = tid & 31;
    const int wid  = tid >> 5;         // warp_m: 4 quadrants of 32 m-rows
    const int mbase = wid * 32;
    const int nh   = blockIdx.x & 1;   // constant across grid-stride iterations

    // ---- load W half-tile [64 n-rows x 320 k] once per CTA ----
    {
        int n = tid >> 1;                     // 0..63 local n-row
        int q0 = (tid & 1) * 20;
#pragma unroll
        for (int q = 0; q < 20; q++) {
            uint4 v = g_wb4[(nh * 64 + n) * 40 + q0 + q];
            *reinterpret_cast<uint4*>(smem + SMEM_W + n * WPITCH + (q0 + q) * 16) = v;
        }
    }
    __syncthreads();   // only barrier: W visible to all warps

    // warp-private stage base
    const uint32_t wstage = smemS + SMEM_STAGE + (uint32_t)wid * WSLOT_BYTES;

    // per-thread ldmatrix base addresses (within warp window; invariant across tiles)
    const uint32_t aBase = wstage + (uint32_t)(lane & 15) * STAGE_PITCH
                         + (uint32_t)(lane >> 4) * 16;
    const uint32_t bBase = smemS + SMEM_W
                         + (uint32_t)((lane & 7) + ((lane >> 4) << 3)) * WPITCH
                         + (uint32_t)((lane >> 3) & 1) * 16;

    // per-warp stage prefetch: 104 uint4 chunks (52 rows x 2) by 32 lanes
    auto prefetch = [&](int unit, int buf) {
        if (unit >= NUNITS) return;
        int ptile = unit >> 1;
        int b  = ptile / NTILE_P;
        int p0 = (ptile % NTILE_P) * TILE_M;
        const uint4* src = &g_pb4[((size_t)b * TP + p0 + mbase) * 2];
        uint32_t dst = wstage + (uint32_t)buf * WSTAGE_BYTES;
#pragma unroll
        for (int c0 = 0; c0 < 96; c0 += 32) {
            int c = c0 + lane;
            cp_async16(dst + (c >> 1) * STAGE_PITCH + (c & 1) * 16, src + c);
        }
        if (lane < 8) {
            int c = 96 + lane;
            cp_async16(dst + (c >> 1) * STAGE_PITCH + (c & 1) * 16, src + c);
        }
        cp_async_commit();
    };

    int unit = blockIdx.x;
    prefetch(unit, 0);
    int buf = 0;

    for (; unit < NUNITS; unit += GRID, buf ^= 1) {
        cp_async_wait0();
        __syncwarp();                          // stage visible within the warp
        prefetch(unit + GRID, buf ^ 1);        // overlap next stage load with compute

        int ptile = unit >> 1;
        int b  = ptile / NTILE_P;
        int p0 = (ptile % NTILE_P) * TILE_M;
        const uint32_t aB = aBase + (uint32_t)buf * WSTAGE_BYTES;

        float c[2][8][4];
#pragma unroll
        for (int mf = 0; mf < 2; mf++)
#pragma unroll
            for (int nf = 0; nf < 8; nf++)
#pragma unroll
                for (int r = 0; r < 4; r++) c[mf][nf][r] = 0.0f;

#pragma unroll
        for (int s = 0; s < KSTEPS; s++) {
            uint32_t a[2][4];
#pragma unroll
            for (int mf = 0; mf < 2; mf++)
                ldmatrix_x4(a[mf], aB + (uint32_t)s * STAGE_PITCH + (uint32_t)mf * (16 * STAGE_PITCH));

            uint32_t bb[8][2];
#pragma unroll
            for (int nb = 0; nb < 4; nb++) {
                uint32_t r4[4];
                ldmatrix_x4(r4, bBase + (uint32_t)s * 32 + (uint32_t)nb * (16 * WPITCH));
                bb[2 * nb][0]     = r4[0];
                bb[2 * nb][1]     = r4[1];
                bb[2 * nb + 1][0] = r4[2];
                bb[2 * nb + 1][1] = r4[3];
            }

#pragma unroll
            for (int mf = 0; mf < 2; mf++)
#pragma unroll
                for (int nf = 0; nf < 8; nf++)
                    mma_bf16(c[mf][nf], a[mf], bb[nf]);
        }

        // ---- epilogue: c(row p', col n_local) -> out[b][nh*64 + n][p0 + p'] ----
        // Streaming (evict-first) stores keep the 654MB output stream out of L2's way.
        float* outb = out + (size_t)b * NN * POUT + (size_t)(nh * 64) * POUT;
        int pq = p0 + mbase + (lane >> 2);
        int nc = (lane & 3) * 2;
#pragma unroll
        for (int mf = 0; mf < 2; mf++) {
#pragma unroll
            for (int half = 0; half < 2; half++) {
                int p = pq + mf * 16 + half * 8;
                if (p < POUT) {
#pragma unroll
                    for (int nf = 0; nf < 8; nf++) {
                        int n = nc + nf * 8;
                        __stcs(&outb[(size_t)n * POUT + p],       c[mf][nf][half * 2]);
                        __stcs(&outb[(size_t)(n + 1) * POUT + p], c[mf][nf][half * 2 + 1]);
                    }
                }
            }
        }
        // no CTA barrier: warp-private stage, per-warp cp.async groups
    }
}

// ---------------- launch ----------------
extern "C" void kernel_launch(void* const* d_in, const int* in_sizes, int n_in,
                              void* d_out, int out_size) {
    const float* x = (const float*)d_in[0];
    const float* W = (const float*)d_in[1];
    if (n_in >= 2 && in_sizes[0] == KK * CC * CC * NN && in_sizes[1] == BB * CC * LL) {
        const float* t = x; x = W; W = t;   // defensive: swapped order
    }
    float* out = (float*)d_out;

    prep_all_kernel<<<(BB * TP + 127) / 128, 128>>>(x, W);

    cudaFuncSetAttribute(markonv_hmma_kernel, cudaFuncAttributeMaxDynamicSharedMemorySize, SMEM_TOTAL);
    markonv_hmma_kernel<<<GRID, 128, SMEM_TOTAL>>>(out);
}

// round 13
// speedup vs baseline: 1.1216x; 1.1216x over previous
#include <cuda_runtime.h>
#include <cuda_bf16.h>
#include <cstdint>

// ---------------- problem constants ----------------
#define BB     128
#define CC     4
#define LL     10000
#define KK     20
#define NN     128
#define POUT   9980            // ceil((L-K)/stride), stride=1
#define TP     10016           // padded pair-row count (t in [0, 9998], zero-padded)
#define TILE_M 128
#define NTILE_P 78             // ceil(9980/128)
#define NUNITS (BB * NTILE_P * 2)  // 19968 work units (p-tile x n-half)
#define KSTEPS 20              // 320 / 16
#define GRID   444             // 3 CTAs/SM x 148 SMs (R10 proven config)

// ---------------- device scratch (static, no runtime alloc) ----------------
__device__ uint4 g_pb4[(size_t)BB * TP * 2];   // pair bf16 [b][t][16], 2 x uint4 per row
__device__ uint4 g_wb4[NN * 40];               // W bf16 [n][320], 40 x uint4 per n-row

// ---------------- smem layout (dynamic) ----------------
#define STAGE_ROWS  148
#define STAGE_PITCH 48
#define STAGE_BYTES (STAGE_ROWS * STAGE_PITCH)     // 7104
#define SMEM_STAGE  0                              // [2][7104]
#define SMEM_W      (2 * STAGE_BYTES)              // 14208
#define WPITCH      656                            // 328 bf16 per n-row (8-elem pad)
#define SMEM_TOTAL  (SMEM_W + 64 * WPITCH)         // 56192 (x3 CTAs = 168576)

// ---------------- helpers ----------------
__device__ __forceinline__ uint32_t smem_u32(const void* p) {
    uint32_t a;
    asm("{ .reg .u64 t; cvta.to.shared.u64 t, %1; cvt.u32.u64 %0, t; }" : "=r"(a) : "l"(p));
    return a;
}
__device__ __forceinline__ void ldmatrix_x4(uint32_t* r, uint32_t addr) {
    asm volatile("ldmatrix.sync.aligned.m8n8.x4.shared.b16 {%0,%1,%2,%3}, [%4];"
                 : "=r"(r[0]), "=r"(r[1]), "=r"(r[2]), "=r"(r[3]) : "r"(addr));
}
__device__ __forceinline__ void mma_bf16(float* c, const uint32_t* a, const uint32_t* b) {
    asm volatile(
        "mma.sync.aligned.m16n8k16.row.col.f32.bf16.bf16.f32 "
        "{%0,%1,%2,%3}, {%4,%5,%6,%7}, {%8,%9}, {%0,%1,%2,%3};"
        : "+f"(c[0]), "+f"(c[1]), "+f"(c[2]), "+f"(c[3])
        : "r"(a[0]), "r"(a[1]), "r"(a[2]), "r"(a[3]), "r"(b[0]), "r"(b[1]));
}
__device__ __forceinline__ void cp_async16(uint32_t saddr, const void* gaddr) {
    asm volatile("cp.async.ca.shared.global [%0], [%1], 16;" :: "r"(saddr), "l"(gaddr) : "memory");
}
__device__ __forceinline__ void cp_async_commit() {
    asm volatile("cp.async.commit_group;" ::: "memory");
}
__device__ __forceinline__ void cp_async_wait0() {
    asm volatile("cp.async.wait_group 0;" ::: "memory");
}

// ---------------- merged prep kernel ----------------
__global__ void prep_all_kernel(const float* __restrict__ x, const float* __restrict__ W) {
    int gid = blockIdx.x * blockDim.x + threadIdx.x;   // gid = b*TP + t
    if (gid < BB * TP) {
        int b = gid / TP;
        int t = gid % TP;
        uint4 lo = make_uint4(0, 0, 0, 0), hi = lo;
        if (t <= LL - 2) {
            float xa[4], xb[4];
#pragma unroll
            for (int i = 0; i < 4; i++) xa[i] = x[((size_t)b * CC + i) * LL + t];
#pragma unroll
            for (int j = 0; j < 4; j++) xb[j] = x[((size_t)b * CC + j) * LL + t + 1];
            unsigned u[8];
#pragma unroll
            for (int i = 0; i < 4; i++) {
#pragma unroll
                for (int jh = 0; jh < 2; jh++) {
                    __nv_bfloat162 h = __floats2bfloat162_rn(xa[i] * xb[2 * jh], xa[i] * xb[2 * jh + 1]);
                    u[i * 2 + jh] = *reinterpret_cast<unsigned*>(&h);
                }
            }
            lo = make_uint4(u[0], u[1], u[2], u[3]);
            hi = make_uint4(u[4], u[5], u[6], u[7]);
        }
        g_pb4[(size_t)gid * 2]     = lo;
        g_pb4[(size_t)gid * 2 + 1] = hi;
    }
    if (gid < KK * CC * CC * NN) {
        int n = gid / 320;
        int rem = gid % 320;            // rem = l*16 + (i*4 + j)
        int l = rem >> 4;
        int c = rem & 15;
        int i = c >> 2, j = c & 3;
        float v = W[(((l * CC + i) * CC + j) * NN) + n];
        reinterpret_cast<__nv_bfloat16*>(g_wb4)[gid] = __float2bfloat16(v);
    }
}

// ---------------- main persistent GEMM kernel ----------------
// Work unit: 128 p-rows x 64 n-cols; 4 warps, each warp = 32 p x 64 n.
// OPERAND-SWAPPED mma: A = W[n][k] (16 n-rows), B = pair[p][k] (8 p-cols).
// out[n][p] fragment holds (n,p),(n,p+1) -> contiguous-p STG.64 epilogue.
// A[.][s*16+c] = W rows; B rows = stage[p + s][c]; im2col never materialized.
__global__ void __launch_bounds__(128, 3) markonv_hmma_kernel(float* __restrict__ out) {
    extern __shared__ char smem[];
    const uint32_t smemS = smem_u32(smem);
    const int tid  = threadIdx.x;
    const int lane = tid & 31;
    const int wid  = tid >> 5;         // warp_p: 4 quadrants of 32 p-rows
    const int mbase = wid * 32;        // p offset of this warp within the tile
    const int nh   = blockIdx.x & 1;   // constant across grid-stride iterations (444 even)

    // ---- load W half-tile [64 n-rows x 320 k] once per CTA ----
    {
        int n = tid >> 1;                     // 0..63 local n-row
        int q0 = (tid & 1) * 20;
#pragma unroll
        for (int q = 0; q < 20; q++) {
            uint4 v = g_wb4[(nh * 64 + n) * 40 + q0 + q];
            *reinterpret_cast<uint4*>(smem + SMEM_W + n * WPITCH + (q0 + q) * 16) = v;
        }
    }

    // per-thread ldmatrix base addresses (invariant across tiles)
    // A-operand (W): 16-row x4 pattern (rows = n)
    const uint32_t wBase = smemS + SMEM_W + (uint32_t)(lane & 15) * WPITCH
                         + (uint32_t)(lane >> 4) * 16;
    // B-operand (pair stage): B-permutation (rows = p within warp window)
    const uint32_t pBase = smemS + SMEM_STAGE
                         + (uint32_t)(mbase + (lane & 7) + ((lane >> 4) << 3)) * STAGE_PITCH
                         + (uint32_t)((lane >> 3) & 1) * 16;

    // stage-copy slots: 296 uint4 chunks (148 rows x 2) by 128 threads
    const int idx0 = tid;
    const int idx1 = tid + 128;
    const int idx2 = tid + 256;        // valid for tid < 40
    const uint32_t sD0 = smemS + SMEM_STAGE + (idx0 >> 1) * STAGE_PITCH + (idx0 & 1) * 16;
    const uint32_t sD1 = smemS + SMEM_STAGE + (idx1 >> 1) * STAGE_PITCH + (idx1 & 1) * 16;
    const uint32_t sD2 = smemS + SMEM_STAGE + (idx2 >> 1) * STAGE_PITCH + (idx2 & 1) * 16;

    auto prefetch = [&](int unit, int buf) {
        if (unit >= NUNITS) return;
        int ptile = unit >> 1;
        int b  = ptile / NTILE_P;
        int p0 = (ptile % NTILE_P) * TILE_M;
        const uint4* src = &g_pb4[((size_t)b * TP + p0) * 2];
        uint32_t bofs = (uint32_t)buf * STAGE_BYTES;
        cp_async16(sD0 + bofs, src + idx0);
        cp_async16(sD1 + bofs, src + idx1);
        if (idx2 < 2 * STAGE_ROWS) cp_async16(sD2 + bofs, src + idx2);
        cp_async_commit();
    };

    int unit = blockIdx.x;
    prefetch(unit, 0);
    int buf = 0;

    for (; unit < NUNITS; unit += GRID, buf ^= 1) {
        cp_async_wait0();
        __syncthreads();
        prefetch(unit + GRID, buf ^ 1);

        int ptile = unit >> 1;
        int b  = ptile / NTILE_P;
        int p0 = (ptile % NTILE_P) * TILE_M;
        const uint32_t pB = pBase + (uint32_t)buf * STAGE_BYTES;

        float c[4][4][4];                  // [n-frag 16][p-frag 8][4]
#pragma unroll
        for (int i = 0; i < 4; i++)
#pragma unroll
            for (int pf = 0; pf < 4; pf++)
#pragma unroll
                for (int r = 0; r < 4; r++) c[i][pf][r] = 0.0f;

#pragma unroll
        for (int s = 0; s < KSTEPS; s++) {
            uint32_t a[4][4];              // W frags: 4 n-blocks of 16
#pragma unroll
            for (int i = 0; i < 4; i++)
                ldmatrix_x4(a[i], wBase + (uint32_t)i * (16 * WPITCH) + (uint32_t)s * 32);

            uint32_t bb[4][2];             // pair frags: 4 p-blocks of 8
#pragma unroll
            for (int j = 0; j < 2; j++) {
                uint32_t r4[4];
                ldmatrix_x4(r4, pB + (uint32_t)(j * 16 + s) * STAGE_PITCH);
                bb[2 * j][0]     = r4[0];
                bb[2 * j][1]     = r4[1];
                bb[2 * j + 1][0] = r4[2];
                bb[2 * j + 1][1] = r4[3];
            }

#pragma unroll
            for (int i = 0; i < 4; i++)
#pragma unroll
                for (int pf = 0; pf < 4; pf++)
                    mma_bf16(c[i][pf], a[i], bb[pf]);
        }

        // ---- epilogue: c(n-row, p-col) -> out[b][nh*64 + n][p0 + mbase + p] ----
        // Fragment holds (n,p),(n,p+1) pairs -> STG.64 streaming stores.
        float* outb = out + (size_t)b * NN * POUT + (size_t)(nh * 64) * POUT;
        int nrow = lane >> 2;              // + i*16, +8
        int pcol = p0 + mbase + (lane & 3) * 2;   // + pf*8
#pragma unroll
        for (int i = 0; i < 4; i++) {
            int n0r = i * 16 + nrow;
#pragma unroll
            for (int pf = 0; pf < 4; pf++) {
                int p = pcol + pf * 8;
                if (p < POUT) {            // p even, POUT even -> p+1 also valid
                    __stcs(reinterpret_cast<float2*>(&outb[(size_t)n0r * POUT + p]),
                           make_float2(c[i][pf][0], c[i][pf][1]));
                    __stcs(reinterpret_cast<float2*>(&outb[(size_t)(n0r + 8) * POUT + p]),
                           make_float2(c[i][pf][2], c[i][pf][3]));
                }
            }
        }
        __syncthreads();   // all reads of `buf` done before refill (2 units ahead)
    }
}

// ---------------- launch ----------------
extern "C" void kernel_launch(void* const* d_in, const int* in_sizes, int n_in,
                              void* d_out, int out_size) {
    const float* x = (const float*)d_in[0];
    const float* W = (const float*)d_in[1];
    if (n_in >= 2 && in_sizes[0] == KK * CC * CC * NN && in_sizes[1] == BB * CC * LL) {
        const float* t = x; x = W; W = t;   // defensive: swapped order
    }
    float* out = (float*)d_out;

    prep_all_kernel<<<(BB * TP + 127) / 128, 128>>>(x, W);

    cudaFuncSetAttribute(markonv_hmma_kernel, cudaFuncAttributeMaxDynamicSharedMemorySize, SMEM_TOTAL);
    markonv_hmma_kernel<<<GRID, 128, SMEM_TOTAL>>>(out);
}

// round 16
// speedup vs baseline: 1.1673x; 1.0407x over previous
#include <cuda_runtime.h>
#include <cuda_bf16.h>
#include <cstdint>

// ---------------- problem constants ----------------
#define BB     128
#define CC     4
#define LL     10000
#define KK     20
#define NN     128
#define POUT   9980            // ceil((L-K)/stride), stride=1
#define TP     10016           // padded pair-row count (t in [0, 9998], zero-padded)
#define TILE_M 128
#define NTILE_P 78             // ceil(9980/128)
#define NUNITS (BB * NTILE_P * 2)  // 19968 work units (p-tile x n-half)
#define KSTEPS 20              // 320 / 16
#define GRID   444             // 3 CTAs/SM x 148 SMs (proven R10 config)

// ---------------- device scratch (static, no runtime alloc) ----------------
__device__ uint4 g_pb4[(size_t)BB * TP * 2];   // pair bf16 [b][t][16], 2 x uint4 per row
__device__ uint4 g_wb4[NN * 40];               // W bf16 [n][320], 40 x uint4 per n-row

// ---------------- smem layout (dynamic) ----------------
#define STAGE_ROWS  148
#define STAGE_PITCH 48
#define STAGE_BYTES (STAGE_ROWS * STAGE_PITCH)     // 7104
#define SMEM_STAGE  0                              // [2][7104]
#define SMEM_W      (2 * STAGE_BYTES)              // 14208
#define WPITCH      656                            // 328 bf16 per n-row (8-elem pad)
#define SMEM_TOTAL  (SMEM_W + 64 * WPITCH)         // 56192 (x3 CTAs = 168576)

// ---------------- helpers ----------------
__device__ __forceinline__ uint32_t smem_u32(const void* p) {
    uint32_t a;
    asm("{ .reg .u64 t; cvta.to.shared.u64 t, %1; cvt.u32.u64 %0, t; }" : "=r"(a) : "l"(p));
    return a;
}
__device__ __forceinline__ void ldmatrix_x4(uint32_t* r, uint32_t addr) {
    asm volatile("ldmatrix.sync.aligned.m8n8.x4.shared.b16 {%0,%1,%2,%3}, [%4];"
                 : "=r"(r[0]), "=r"(r[1]), "=r"(r[2]), "=r"(r[3]) : "r"(addr));
}
__device__ __forceinline__ void mma_bf16(float* c, const uint32_t* a, const uint32_t* b) {
    asm volatile(
        "mma.sync.aligned.m16n8k16.row.col.f32.bf16.bf16.f32 "
        "{%0,%1,%2,%3}, {%4,%5,%6,%7}, {%8,%9}, {%0,%1,%2,%3};"
        : "+f"(c[0]), "+f"(c[1]), "+f"(c[2]), "+f"(c[3])
        : "r"(a[0]), "r"(a[1]), "r"(a[2]), "r"(a[3]), "r"(b[0]), "r"(b[1]));
}
__device__ __forceinline__ void cp_async16(uint32_t saddr, const void* gaddr) {
    asm volatile("cp.async.ca.shared.global [%0], [%1], 16;" :: "r"(saddr), "l"(gaddr) : "memory");
}
__device__ __forceinline__ void cp_async_commit() {
    asm volatile("cp.async.commit_group;" ::: "memory");
}
__device__ __forceinline__ void cp_async_wait0() {
    asm volatile("cp.async.wait_group 0;" ::: "memory");
}

// ---------------- merged prep kernel ----------------
__global__ void prep_all_kernel(const float* __restrict__ x, const float* __restrict__ W) {
    int gid = blockIdx.x * blockDim.x + threadIdx.x;   // gid = b*TP + t
    if (gid < BB * TP) {
        int b = gid / TP;
        int t = gid % TP;
        uint4 lo = make_uint4(0, 0, 0, 0), hi = lo;
        if (t <= LL - 2) {
            float xa[4], xb[4];
#pragma unroll
            for (int i = 0; i < 4; i++) xa[i] = x[((size_t)b * CC + i) * LL + t];
#pragma unroll
            for (int j = 0; j < 4; j++) xb[j] = x[((size_t)b * CC + j) * LL + t + 1];
            unsigned u[8];
#pragma unroll
            for (int i = 0; i < 4; i++) {
#pragma unroll
                for (int jh = 0; jh < 2; jh++) {
                    __nv_bfloat162 h = __floats2bfloat162_rn(xa[i] * xb[2 * jh], xa[i] * xb[2 * jh + 1]);
                    u[i * 2 + jh] = *reinterpret_cast<unsigned*>(&h);
                }
            }
            lo = make_uint4(u[0], u[1], u[2], u[3]);
            hi = make_uint4(u[4], u[5], u[6], u[7]);
        }
        g_pb4[(size_t)gid * 2]     = lo;
        g_pb4[(size_t)gid * 2 + 1] = hi;
    }
    if (gid < KK * CC * CC * NN) {
        int n = gid / 320;
        int rem = gid % 320;            // rem = l*16 + (i*4 + j)
        int l = rem >> 4;
        int c = rem & 15;
        int i = c >> 2, j = c & 3;
        float v = W[(((l * CC + i) * CC + j) * NN) + n];
        reinterpret_cast<__nv_bfloat16*>(g_wb4)[gid] = __float2bfloat16(v);
    }
}

// ---------------- main persistent GEMM kernel ----------------
// Work unit: 128 p-rows x 64 n-cols. 4 warps, each 32m x 64n (R10 proven shape).
// A[m][s*16+c] = stage[m+s][c]; im2col never materialized.
// NEW vs R10: explicit fragment double-buffering — step s+1's ldmatrix issue
// before step s's MMAs, so the LDS latency at each k-step boundary is covered
// by the current step's tensor work.
__global__ void __launch_bounds__(128, 3) markonv_hmma_kernel(float* __restrict__ out) {
    extern __shared__ char smem[];
    const uint32_t smemS = smem_u32(smem);
    const int tid  = threadIdx.x;
    const int lane = tid & 31;
    const int wid  = tid >> 5;         // warp_m: 4 quadrants of 32 m-rows
    const int mbase = wid * 32;
    const int nh   = blockIdx.x & 1;   // constant across grid-stride iterations (444 even)

    // ---- load W half-tile [64 n-rows x 320 k] once per CTA ----
    {
        int n = tid >> 1;                     // 0..63 local n-row
        int q0 = (tid & 1) * 20;
#pragma unroll
        for (int q = 0; q < 20; q++) {
            uint4 v = g_wb4[(nh * 64 + n) * 40 + q0 + q];
            *reinterpret_cast<uint4*>(smem + SMEM_W + n * WPITCH + (q0 + q) * 16) = v;
        }
    }

    // per-thread ldmatrix base addresses (invariant across tiles)
    const uint32_t aBase = smemS + SMEM_STAGE + (uint32_t)(mbase + (lane & 15)) * STAGE_PITCH
                         + (uint32_t)(lane >> 4) * 16;
    const uint32_t bBase = smemS + SMEM_W
                         + (uint32_t)((lane & 7) + ((lane >> 4) << 3)) * WPITCH
                         + (uint32_t)((lane >> 3) & 1) * 16;

    // stage-copy slots: 296 uint4 chunks (148 rows x 2) by 128 threads
    const int idx0 = tid;
    const int idx1 = tid + 128;
    const int idx2 = tid + 256;        // valid for tid < 40
    const uint32_t sD0 = smemS + SMEM_STAGE + (idx0 >> 1) * STAGE_PITCH + (idx0 & 1) * 16;
    const uint32_t sD1 = smemS + SMEM_STAGE + (idx1 >> 1) * STAGE_PITCH + (idx1 & 1) * 16;
    const uint32_t sD2 = smemS + SMEM_STAGE + (idx2 >> 1) * STAGE_PITCH + (idx2 & 1) * 16;

    auto prefetch = [&](int unit, int buf) {
        if (unit >= NUNITS) return;
        int ptile = unit >> 1;
        int b  = ptile / NTILE_P;
        int p0 = (ptile % NTILE_P) * TILE_M;
        const uint4* src = &g_pb4[((size_t)b * TP + p0) * 2];
        uint32_t bofs = (uint32_t)buf * STAGE_BYTES;
        cp_async16(sD0 + bofs, src + idx0);
        cp_async16(sD1 + bofs, src + idx1);
        if (idx2 < 2 * STAGE_ROWS) cp_async16(sD2 + bofs, src + idx2);
        cp_async_commit();
    };

    // fragment loaders (step s into buffer slot)
    auto load_a = [&](uint32_t aB, int s, uint32_t (*a)[4]) {
#pragma unroll
        for (int mf = 0; mf < 2; mf++)
            ldmatrix_x4(a[mf], aB + (uint32_t)s * STAGE_PITCH + (uint32_t)mf * (16 * STAGE_PITCH));
    };
    auto load_b = [&](int s, uint32_t (*bb)[2]) {
#pragma unroll
        for (int nb = 0; nb < 4; nb++) {
            uint32_t r4[4];
            ldmatrix_x4(r4, bBase + (uint32_t)s * 32 + (uint32_t)nb * (16 * WPITCH));
            bb[2 * nb][0]     = r4[0];
            bb[2 * nb][1]     = r4[1];
            bb[2 * nb + 1][0] = r4[2];
            bb[2 * nb + 1][1] = r4[3];
        }
    };

    int unit = blockIdx.x;
    prefetch(unit, 0);
    int buf = 0;

    for (; unit < NUNITS; unit += GRID, buf ^= 1) {
        cp_async_wait0();
        __syncthreads();
        prefetch(unit + GRID, buf ^ 1);

        int ptile = unit >> 1;
        int b  = ptile / NTILE_P;
        int p0 = (ptile % NTILE_P) * TILE_M;
        const uint32_t aB = aBase + (uint32_t)buf * STAGE_BYTES;

        float c[2][8][4];
#pragma unroll
        for (int mf = 0; mf < 2; mf++)
#pragma unroll
            for (int nf = 0; nf < 8; nf++)
#pragma unroll
                for (int r = 0; r < 4; r++) c[mf][nf][r] = 0.0f;

        // ---- software-pipelined k-loop: frags double-buffered in registers ----
        uint32_t a[2][2][4];     // [slot][mf][4]
        uint32_t bb[2][8][2];    // [slot][nf][2]
        load_a(aB, 0, a[0]);
        load_b(0, bb[0]);

#pragma unroll
        for (int s = 0; s < KSTEPS; s++) {
            const int cur = s & 1, nxt = cur ^ 1;
            if (s + 1 < KSTEPS) {
                load_a(aB, s + 1, a[nxt]);
                load_b(s + 1, bb[nxt]);
            }
#pragma unroll
            for (int mf = 0; mf < 2; mf++)
#pragma unroll
                for (int nf = 0; nf < 8; nf++)
                    mma_bf16(c[mf][nf], a[cur][mf], bb[cur][nf]);
        }

        // ---- epilogue: c(row p', col n_local) -> out[b][nh*64 + n][p0 + p'] ----
        float* outb = out + (size_t)b * NN * POUT + (size_t)(nh * 64) * POUT;
        int pq = p0 + mbase + (lane >> 2);
        int nc = (lane & 3) * 2;
#pragma unroll
        for (int mf = 0; mf < 2; mf++) {
#pragma unroll
            for (int half = 0; half < 2; half++) {
                int p = pq + mf * 16 + half * 8;
                if (p < POUT) {
#pragma unroll
                    for (int nf = 0; nf < 8; nf++) {
                        int n = nc + nf * 8;
                        __stcs(&outb[(size_t)n * POUT + p],       c[mf][nf][half * 2]);
                        __stcs(&outb[(size_t)(n + 1) * POUT + p], c[mf][nf][half * 2 + 1]);
                    }
                }
            }
        }
        __syncthreads();   // all reads of `buf` done before refill (2 units ahead)
    }
}

// ---------------- launch ----------------
extern "C" void kernel_launch(void* const* d_in, const int* in_sizes, int n_in,
                              void* d_out, int out_size) {
    const float* x = (const float*)d_in[0];
    const float* W = (const float*)d_in[1];
    if (n_in >= 2 && in_sizes[0] == KK * CC * CC * NN && in_sizes[1] == BB * CC * LL) {
        const float* t = x; x = W; W = t;   // defensive: swapped order
    }
    float* out = (float*)d_out;

    prep_all_kernel<<<(BB * TP + 127) / 128, 128>>>(x, W);

    cudaFuncSetAttribute(markonv_hmma_kernel, cudaFuncAttributeMaxDynamicSharedMemorySize, SMEM_TOTAL);
    markonv_hmma_kernel<<<GRID, 128, SMEM_TOTAL>>>(out);
}